// round 13
// baseline (speedup 1.0000x reference)
#include <cuda_runtime.h>
#include <cuda_fp16.h>
#include <math.h>

#define BATCH   32
#define NTOK    197
#define DIM     768
#define HEADS   12
#define HD      64
#define MLPD    3072
#define DEPTH   12
#define ROWS    (BATCH*NTOK)     // 6304
#define NPATCH  196
#define PROWS   (BATCH*NPATCH)   // 6272
#define ATTN_SCALE 0.125f
#define MPAD    6400             // padded M for split activation buffers

// ---------------- scratch (no cudaMalloc allowed) ----------------
__device__ float    g_patches[PROWS*DIM];
__device__ float    g_h     [ROWS*DIM];
__device__ float    g_ln    [ROWS*DIM];
__device__ float    g_qkv   [ROWS*3*DIM];
__device__ float    g_attno [ROWS*DIM];
__device__ float    g_cls   [BATCH*DIM];
__device__ unsigned gAh[384*MPAD],  gAl[384*MPAD];    // split activations (K<=768)
__device__ unsigned gMh[1536*MPAD], gMl[1536*MPAD];   // split MLP mid (K=3072)
__device__ unsigned gWh[1179648],   gWl[1179648];     // split weights (max 384*3072)

// ---------------- helpers ----------------
__device__ __forceinline__ float gelu_exact(float x) {
    return 0.5f * x * (1.0f + erff(x * 0.70710678118654752f));
}
// pack two floats as f16x2: first arg -> low 16 bits (even k)
__device__ __forceinline__ unsigned pack2h(float lo, float hi) {
    unsigned r;
    asm("cvt.rn.f16x2.f32 %0, %1, %2;" : "=r"(r) : "f"(hi), "f"(lo));
    return r;
}
__device__ __forceinline__ float f16hi_of(float x) {
    __half h = __float2half_rn(x);
    return __half2float(h);
}

// block reduce over 256 threads. do_max=true -> max else sum.
__device__ __forceinline__ float blk_reduce256(float v, bool do_max, float* red) {
    #pragma unroll
    for (int off = 16; off; off >>= 1) {
        float o = __shfl_xor_sync(0xffffffffu, v, off);
        v = do_max ? fmaxf(v, o) : (v + o);
    }
    int w = threadIdx.x >> 5;
    if ((threadIdx.x & 31) == 0) red[w] = v;
    __syncthreads();
    if (threadIdx.x < 32) {
        v = red[threadIdx.x & 7];
        #pragma unroll
        for (int off = 4; off; off >>= 1) {
            float o = __shfl_xor_sync(0xffffffffu, v, off);
            v = do_max ? fmaxf(v, o) : (v + o);
        }
        if (threadIdx.x == 0) red[0] = v;
    }
    __syncthreads();
    float r = red[0];
    __syncthreads();
    return r;
}

// ---------------- patch gather ----------------
__global__ void gather_patches_kernel(const float* __restrict__ x, float* __restrict__ P) {
    int idx = blockIdx.x * blockDim.x + threadIdx.x;
    int total = PROWS * DIM;
    if (idx >= total) return;
    int m = idx / DIM, k = idx - m * DIM;
    int b = m / NPATCH, t = m - b * NPATCH;
    int ph = t / 14, pw = t - ph * 14;
    int c = k >> 8, r = k & 255;
    int py = r >> 4, px = r & 15;
    int h = ph * 16 + py, w = pw * 16 + px;
    P[idx] = x[(((long)b * 3 + c) * 224 + h) * 224 + w];
}

// ---------------- assemble h = [cls ; tok] + pos ----------------
__global__ void embed_kernel(const float* __restrict__ tok, const float* __restrict__ cls,
                             const float* __restrict__ pos, float* __restrict__ h) {
    int idx = blockIdx.x * blockDim.x + threadIdx.x;
    int total = ROWS * DIM;
    if (idx >= total) return;
    int rd = idx % (NTOK * DIM);
    int b  = idx / (NTOK * DIM);
    int n  = rd / DIM, d = rd - n * DIM;
    float base = (n == 0) ? cls[d] : tok[((long)b * NPATCH + (n - 1)) * DIM + d];
    h[idx] = base + pos[n * DIM + d];
}

// ---------------- layernorm (fp32 out) ----------------
__global__ void ln_kernel(const float* __restrict__ x, long row_stride,
                          const float* __restrict__ w, const float* __restrict__ b,
                          float* __restrict__ y) {
    __shared__ float red[8];
    long row = blockIdx.x;
    const float* xr = x + row * row_stride;
    int tid = threadIdx.x;
    float v[3], s = 0.f, ss = 0.f;
    #pragma unroll
    for (int i = 0; i < 3; i++) {
        float t = xr[tid + i * 256];
        v[i] = t; s += t; ss += t * t;
    }
    s  = blk_reduce256(s,  false, red);
    ss = blk_reduce256(ss, false, red);
    float mu  = s * (1.0f / 768.0f);
    float var = ss * (1.0f / 768.0f) - mu * mu;
    float inv = rsqrtf(var + 1e-5f);
    #pragma unroll
    for (int i = 0; i < 3; i++) {
        int d = tid + i * 256;
        y[row * DIM + d] = (v[i] - mu) * inv * w[d] + b[d];
    }
}

// ---------------- split+transpose: src[M][K] fp32 -> hiT/loT [K/2][outpitch] f16x2 ----------------
__global__ __launch_bounds__(256) void split_transpose_kernel(
        const float* __restrict__ src, unsigned* __restrict__ hiT, unsigned* __restrict__ loT,
        int Mrows, int K, int outpitch) {
    __shared__ unsigned th[32][33], tl[32][33];
    int k20 = blockIdx.x * 32, m0 = blockIdx.y * 32;
    int tx = threadIdx.x & 31, ty = threadIdx.x >> 5;   // ty 0..7
    #pragma unroll
    for (int i = 0; i < 4; i++) {
        int ml = ty + i * 8;
        int m = m0 + ml, k2 = k20 + tx;
        float v0 = 0.f, v1 = 0.f;
        if (m < Mrows) {
            const float* s = src + (long)m * K + 2 * k2;
            v0 = s[0]; v1 = s[1];
        }
        float h0 = f16hi_of(v0), h1 = f16hi_of(v1);
        th[tx][ml] = pack2h(h0, h1);
        tl[tx][ml] = pack2h(v0 - h0, v1 - h1);
    }
    __syncthreads();
    #pragma unroll
    for (int i = 0; i < 4; i++) {
        int k2l = ty + i * 8;
        long o = (long)(k20 + k2l) * outpitch + m0 + tx;
        hiT[o] = th[k2l][tx];
        loT[o] = tl[k2l][tx];
    }
}

// ---------------- 3-term FP16-split tensor-core GEMM (pre-split operands) ----------------
// C[M,N] = A[M,K] @ W[N,K]^T; A = aH+aL exact, W = wH+wL (wL subnormal-limited).
// product = aL*wH + aH*wL + aH*wH. block 128x128x16, 8 warps, warp 64x32 m16n8k16.
#define BM 128
#define BN 128
#define SPITCH 136   // uint pitch; conflict-free fragment loads

__global__ __launch_bounds__(256) void gemm_tc_kernel(
        const unsigned* __restrict__ Ah, const unsigned* __restrict__ Al, int pitchA,
        const unsigned* __restrict__ Wh, const unsigned* __restrict__ Wl, int pitchW,
        const float* __restrict__ bias, const float* __restrict__ resid,
        float* __restrict__ C,
        unsigned* __restrict__ ChiT, unsigned* __restrict__ CloT, int pitchC,
        int M, int N, int K, int act, int splitout) {
    __shared__ unsigned AsH[8][SPITCH];
    __shared__ unsigned AsL[8][SPITCH];
    __shared__ unsigned WsH[8][SPITCH];
    __shared__ unsigned WsL[8][SPITCH];

    int bm = blockIdx.y * BM;
    int bn = blockIdx.x * BN;
    int tid  = threadIdx.x;
    int warp = tid >> 5;
    int lane = tid & 31;
    int g    = lane >> 2;    // 0..7
    int t4   = lane & 3;     // 0..3
    int wm = (warp & 1) * 64;
    int wn = (warp >> 1) * 32;

    // load coords: thread covers one uint4 (16B) per array per k16 tile
    int k2row = tid >> 5;            // 0..7
    int mcol  = (lane) << 2;         // 0..124
    const unsigned* pAh = Ah + (long)k2row * pitchA + bm + mcol;
    const unsigned* pAl = Al + (long)k2row * pitchA + bm + mcol;
    const unsigned* pWh = Wh + (long)k2row * pitchW + bn + mcol;
    const unsigned* pWl = Wl + (long)k2row * pitchW + bn + mcol;

    float acc[4][4][4];
    #pragma unroll
    for (int i = 0; i < 4; i++)
        #pragma unroll
        for (int j = 0; j < 4; j++)
            #pragma unroll
            for (int c = 0; c < 4; c++) acc[i][j][c] = 0.f;

    int T = K >> 4;
    // prefetch tile 0
    uint4 rAh = *(const uint4*)pAh;
    uint4 rAl = *(const uint4*)pAl;
    uint4 rWh = *(const uint4*)pWh;
    uint4 rWl = *(const uint4*)pWl;

    for (int t = 0; t < T; t++) {
        *(uint4*)&AsH[k2row][mcol] = rAh;
        *(uint4*)&AsL[k2row][mcol] = rAl;
        *(uint4*)&WsH[k2row][mcol] = rWh;
        *(uint4*)&WsL[k2row][mcol] = rWl;
        __syncthreads();

        if (t + 1 < T) {
            long o = (long)(t + 1) * 8;
            rAh = *(const uint4*)(pAh + o * pitchA);
            rAl = *(const uint4*)(pAl + o * pitchA);
            rWh = *(const uint4*)(pWh + o * pitchW);
            rWl = *(const uint4*)(pWl + o * pitchW);
        }

        unsigned afH[4][4], afL[4][4];
        unsigned bfH[4][2], bfL[4][2];
        #pragma unroll
        for (int mt = 0; mt < 4; mt++) {
            int m0 = wm + mt * 16;
            afH[mt][0] = AsH[t4    ][m0 + g    ];
            afH[mt][1] = AsH[t4    ][m0 + g + 8];
            afH[mt][2] = AsH[t4 + 4][m0 + g    ];
            afH[mt][3] = AsH[t4 + 4][m0 + g + 8];
            afL[mt][0] = AsL[t4    ][m0 + g    ];
            afL[mt][1] = AsL[t4    ][m0 + g + 8];
            afL[mt][2] = AsL[t4 + 4][m0 + g    ];
            afL[mt][3] = AsL[t4 + 4][m0 + g + 8];
        }
        #pragma unroll
        for (int nt = 0; nt < 4; nt++) {
            int n0 = wn + nt * 8;
            bfH[nt][0] = WsH[t4    ][n0 + g];
            bfH[nt][1] = WsH[t4 + 4][n0 + g];
            bfL[nt][0] = WsL[t4    ][n0 + g];
            bfL[nt][1] = WsL[t4 + 4][n0 + g];
        }
        #pragma unroll
        for (int mt = 0; mt < 4; mt++)
            #pragma unroll
            for (int nt = 0; nt < 4; nt++) {
                asm volatile(
                    "mma.sync.aligned.m16n8k16.row.col.f32.f16.f16.f32 "
                    "{%0,%1,%2,%3}, {%4,%5,%6,%7}, {%8,%9}, {%0,%1,%2,%3};"
                    : "+f"(acc[mt][nt][0]), "+f"(acc[mt][nt][1]),
                      "+f"(acc[mt][nt][2]), "+f"(acc[mt][nt][3])
                    : "r"(afL[mt][0]), "r"(afL[mt][1]), "r"(afL[mt][2]), "r"(afL[mt][3]),
                      "r"(bfH[nt][0]), "r"(bfH[nt][1]));
                asm volatile(
                    "mma.sync.aligned.m16n8k16.row.col.f32.f16.f16.f32 "
                    "{%0,%1,%2,%3}, {%4,%5,%6,%7}, {%8,%9}, {%0,%1,%2,%3};"
                    : "+f"(acc[mt][nt][0]), "+f"(acc[mt][nt][1]),
                      "+f"(acc[mt][nt][2]), "+f"(acc[mt][nt][3])
                    : "r"(afH[mt][0]), "r"(afH[mt][1]), "r"(afH[mt][2]), "r"(afH[mt][3]),
                      "r"(bfL[nt][0]), "r"(bfL[nt][1]));
                asm volatile(
                    "mma.sync.aligned.m16n8k16.row.col.f32.f16.f16.f32 "
                    "{%0,%1,%2,%3}, {%4,%5,%6,%7}, {%8,%9}, {%0,%1,%2,%3};"
                    : "+f"(acc[mt][nt][0]), "+f"(acc[mt][nt][1]),
                      "+f"(acc[mt][nt][2]), "+f"(acc[mt][nt][3])
                    : "r"(afH[mt][0]), "r"(afH[mt][1]), "r"(afH[mt][2]), "r"(afH[mt][3]),
                      "r"(bfH[nt][0]), "r"(bfH[nt][1]));
            }
        __syncthreads();
    }

    // epilogue
    #pragma unroll
    for (int mt = 0; mt < 4; mt++) {
        int row0 = bm + wm + mt * 16 + g;
        int row1 = row0 + 8;
        #pragma unroll
        for (int nt = 0; nt < 4; nt++) {
            int col = bn + wn + nt * 8 + t4 * 2;
            float bs0 = 0.f, bs1 = 0.f;
            if (bias && col < N)     bs0 = bias[col];
            if (bias && col + 1 < N) bs1 = bias[col + 1];
            #pragma unroll
            for (int half = 0; half < 2; half++) {
                int row = half ? row1 : row0;
                if (row >= M) continue;
                float v0 = acc[mt][nt][half * 2 + 0] + bs0;
                float v1 = acc[mt][nt][half * 2 + 1] + bs1;
                if (resid) {
                    if (col < N)     v0 += resid[(long)row * N + col];
                    if (col + 1 < N) v1 += resid[(long)row * N + col + 1];
                }
                if (act == 1) { v0 = gelu_exact(v0); v1 = gelu_exact(v1); }
                if (splitout) {
                    float h0 = f16hi_of(v0), h1 = f16hi_of(v1);
                    long o = (long)(col >> 1) * pitchC + row;
                    ChiT[o] = pack2h(h0, h1);
                    CloT[o] = pack2h(v0 - h0, v1 - h1);
                } else {
                    if (col < N)     C[(long)row * N + col]     = v0;
                    if (col + 1 < N) C[(long)row * N + col + 1] = v1;
                }
            }
        }
    }
}

// ---------------- attention: one block per (b,h) ----------------
#define ATTN_SMEM_FLOATS (NTOK*HD*2 + 64 + 208 + 256 + 8)
__global__ __launch_bounds__(256) void attn_kernel(
        const float* __restrict__ qkv, float* __restrict__ o,
        const float* __restrict__ alpha, const float* __restrict__ beta,
        const float* __restrict__ gamma, int poly) {
    extern __shared__ float sh[];
    float* Ks     = sh;
    float* Vs     = Ks + NTOK * HD;
    float* qs     = Vs + NTOK * HD;
    float* scores = qs + 64;
    float* part   = scores + 208;
    float* red    = part + 256;

    int b = blockIdx.x / HEADS;
    int hh = blockIdx.x - b * HEADS;
    int tid = threadIdx.x;

    const float* kbase = qkv + (long)(b * NTOK) * (3 * DIM) + DIM + hh * HD;
    const float* vbase = kbase + DIM;
    for (int i = tid; i < NTOK * (HD / 4); i += 256) {
        int n = i >> 4, d4 = (i & 15) << 2;
        ((float4*)Ks)[i] = *(const float4*)(kbase + (long)n * (3 * DIM) + d4);
        ((float4*)Vs)[i] = *(const float4*)(vbase + (long)n * (3 * DIM) + d4);
    }
    float ah = alpha[hh], bh = beta[hh], gh = gamma[hh];
    __syncthreads();

    for (int n = 0; n < NTOK; n++) {
        const float* qrow = qkv + (long)(b * NTOK + n) * (3 * DIM) + hh * HD;
        if (tid < HD) qs[tid] = qrow[tid];
        __syncthreads();

        float sraw = 0.f;
        if (tid < NTOK) {
            const float* kr = Ks + tid * HD;
            float d0 = 0.f;
            #pragma unroll 16
            for (int d = 0; d < HD; d++) d0 = fmaf(qs[d], kr[d], d0);
            sraw = d0 * ATTN_SCALE;
        }

        float denom;
        if (poly) {
            float val = 0.f;
            if (tid < NTOK) {
                val = fmaxf(fmaf(ah * sraw, sraw, fmaf(bh, sraw, gh)), 0.f);
                scores[tid] = val;
            }
            denom = blk_reduce256(tid < NTOK ? val : 0.f, false, red) + 1e-6f;
        } else {
            float mx = blk_reduce256(tid < NTOK ? sraw : -1e30f, true, red);
            float p = 0.f;
            if (tid < NTOK) { p = __expf(sraw - mx); scores[tid] = p; }
            denom = blk_reduce256(p, false, red);
        }
        float inv = 1.0f / denom;

        int ch = tid >> 6, d = tid & 63;
        float a0 = 0.f;
        int m0 = ch * 50, m1 = m0 + 50; if (m1 > NTOK) m1 = NTOK;
        #pragma unroll 4
        for (int m = m0; m < m1; m++) a0 = fmaf(scores[m], Vs[m * HD + d], a0);
        part[ch * 64 + d] = a0;
        __syncthreads();
        if (tid < 64) {
            float t = part[tid] + part[64 + tid] + part[128 + tid] + part[192 + tid];
            o[(long)(b * NTOK + n) * DIM + hh * HD + tid] = t * inv;
        }
        __syncthreads();
    }
}

// ---------------- host ----------------
static inline dim3 gemm_grid(int M, int NPADv) {
    return dim3(NPADv / BN, (M + BM - 1) / BM);
}
static inline dim3 split_grid(int M, int K) {
    return dim3(K / 64, (M + 31) / 32);
}

extern "C" void kernel_launch(void* const* d_in, const int* in_sizes, int n_in,
                              void* d_out, int out_size) {
    const float* x        = (const float*)d_in[0];
    const float* patch_w  = (const float*)d_in[1];
    const float* patch_b  = (const float*)d_in[2];
    const float* cls_tok  = (const float*)d_in[3];
    const float* pos_emb  = (const float*)d_in[4];
    const float* ln1_w    = (const float*)d_in[5];
    const float* ln1_b    = (const float*)d_in[6];
    const float* qkv_w    = (const float*)d_in[7];
    const float* proj_w   = (const float*)d_in[8];
    const float* proj_b   = (const float*)d_in[9];
    const float* ln2_w    = (const float*)d_in[10];
    const float* ln2_b    = (const float*)d_in[11];
    const float* mlp_w1   = (const float*)d_in[12];
    const float* mlp_b1   = (const float*)d_in[13];
    const float* mlp_w2   = (const float*)d_in[14];
    const float* mlp_b2   = (const float*)d_in[15];
    const float* alpha    = (const float*)d_in[16];
    const float* beta     = (const float*)d_in[17];
    const float* gamma    = (const float*)d_in[18];
    const float* norm_w   = (const float*)d_in[19];
    const float* norm_b   = (const float*)d_in[20];
    const float* head_w   = (const float*)d_in[21];
    const float* head_b   = (const float*)d_in[22];
    float* out = (float*)d_out;

    float *ph, *hh, *lnb, *qkvb, *ob, *clsb;
    unsigned *ah, *al, *mh, *ml, *wh, *wl;
    cudaGetSymbolAddress((void**)&ph,   g_patches);
    cudaGetSymbolAddress((void**)&hh,   g_h);
    cudaGetSymbolAddress((void**)&lnb,  g_ln);
    cudaGetSymbolAddress((void**)&qkvb, g_qkv);
    cudaGetSymbolAddress((void**)&ob,   g_attno);
    cudaGetSymbolAddress((void**)&clsb, g_cls);
    cudaGetSymbolAddress((void**)&ah,   gAh);
    cudaGetSymbolAddress((void**)&al,   gAl);
    cudaGetSymbolAddress((void**)&mh,   gMh);
    cudaGetSymbolAddress((void**)&ml,   gMl);
    cudaGetSymbolAddress((void**)&wh,   gWh);
    cudaGetSymbolAddress((void**)&wl,   gWl);

    const int attn_smem = ATTN_SMEM_FLOATS * sizeof(float);
    cudaFuncSetAttribute(attn_kernel, cudaFuncAttributeMaxDynamicSharedMemorySize, attn_smem);

    // 1) patchify -> split -> patch GEMM -> embed
    {
        int total = PROWS * DIM;
        gather_patches_kernel<<<(total + 255) / 256, 256>>>(x, ph);
        split_transpose_kernel<<<split_grid(PROWS, 768), 256>>>(ph, ah, al, PROWS, 768, MPAD);
        split_transpose_kernel<<<split_grid(768, 768), 256>>>(patch_w, wh, wl, 768, 768, 768);
        gemm_tc_kernel<<<gemm_grid(PROWS, 768), 256>>>(ah, al, MPAD, wh, wl, 768,
                                                       patch_b, nullptr, qkvb,
                                                       nullptr, nullptr, 0,
                                                       PROWS, 768, 768, 0, 0);
        int tot2 = ROWS * DIM;
        embed_kernel<<<(tot2 + 255) / 256, 256>>>(qkvb, cls_tok, pos_emb, hh);
    }

    // 2) transformer layers
    for (int i = 0; i < DEPTH; i++) {
        int poly = (i % 2 == 0) ? 1 : 0;   // MASK = (T,F,T,F,...)
        // --- attention block ---
        ln_kernel<<<ROWS, 256>>>(hh, DIM, ln1_w + (long)i * DIM, ln1_b + (long)i * DIM, lnb);
        split_transpose_kernel<<<split_grid(ROWS, 768), 256>>>(lnb, ah, al, ROWS, 768, MPAD);
        split_transpose_kernel<<<split_grid(2304, 768), 256>>>(qkv_w + (long)i * 3 * DIM * DIM,
                                                               wh, wl, 2304, 768, 2304);
        gemm_tc_kernel<<<gemm_grid(ROWS, 2304), 256>>>(ah, al, MPAD, wh, wl, 2304,
                                                       nullptr, nullptr, qkvb,
                                                       nullptr, nullptr, 0,
                                                       ROWS, 2304, 768, 0, 0);
        attn_kernel<<<BATCH * HEADS, 256, attn_smem>>>(qkvb, ob,
                                                       alpha + (long)i * HEADS,
                                                       beta  + (long)i * HEADS,
                                                       gamma + (long)i * HEADS, poly);
        split_transpose_kernel<<<split_grid(ROWS, 768), 256>>>(ob, ah, al, ROWS, 768, MPAD);
        split_transpose_kernel<<<split_grid(768, 768), 256>>>(proj_w + (long)i * DIM * DIM,
                                                              wh, wl, 768, 768, 768);
        gemm_tc_kernel<<<gemm_grid(ROWS, 768), 256>>>(ah, al, MPAD, wh, wl, 768,
                                                      proj_b + (long)i * DIM, hh, hh,
                                                      nullptr, nullptr, 0,
                                                      ROWS, 768, 768, 0, 0);
        // --- MLP block ---
        ln_kernel<<<ROWS, 256>>>(hh, DIM, ln2_w + (long)i * DIM, ln2_b + (long)i * DIM, lnb);
        split_transpose_kernel<<<split_grid(ROWS, 768), 256>>>(lnb, ah, al, ROWS, 768, MPAD);
        split_transpose_kernel<<<split_grid(3072, 768), 256>>>(mlp_w1 + (long)i * MLPD * DIM,
                                                               wh, wl, 3072, 768, 3072);
        gemm_tc_kernel<<<gemm_grid(ROWS, 3072), 256>>>(ah, al, MPAD, wh, wl, 3072,
                                                       mlp_b1 + (long)i * MLPD, nullptr, nullptr,
                                                       mh, ml, MPAD,
                                                       ROWS, 3072, 768, 1 /*gelu*/, 1 /*splitout*/);
        split_transpose_kernel<<<split_grid(768, 3072), 256>>>(mlp_w2 + (long)i * DIM * MLPD,
                                                               wh, wl, 768, 3072, 768);
        gemm_tc_kernel<<<gemm_grid(ROWS, 768), 256>>>(mh, ml, MPAD, wh, wl, 768,
                                                      mlp_b2 + (long)i * DIM, hh, hh,
                                                      nullptr, nullptr, 0,
                                                      ROWS, 768, 3072, 0, 0);
    }

    // 3) final LN on cls rows + head
    ln_kernel<<<BATCH, 256>>>(hh, (long)NTOK * DIM, norm_w, norm_b, clsb);
    split_transpose_kernel<<<split_grid(BATCH, 768), 256>>>(clsb, ah, al, BATCH, 768, MPAD);
    split_transpose_kernel<<<split_grid(1000, 768), 256>>>(head_w, wh, wl, 1000, 768, 1024);
    gemm_tc_kernel<<<gemm_grid(BATCH, 1024), 256>>>(ah, al, MPAD, wh, wl, 1024,
                                                    head_b, nullptr, out,
                                                    nullptr, nullptr, 0,
                                                    BATCH, 1000, 768, 0, 0);
}

// round 14
// speedup vs baseline: 1.5819x; 1.5819x over previous
#include <cuda_runtime.h>
#include <cuda_fp16.h>
#include <math.h>

#define BATCH   32
#define NTOK    197
#define DIM     768
#define HEADS   12
#define HD      64
#define MLPD    3072
#define DEPTH   12
#define ROWS    (BATCH*NTOK)     // 6304
#define NPATCH  196
#define PROWS   (BATCH*NPATCH)   // 6272
#define ATTN_SCALE 0.125f
#define MPAD    6400             // padded M for split activation buffers
#define KP      200              // KsT pitch (floats)

// ---------------- scratch (no cudaMalloc allowed) ----------------
__device__ float    g_patches[PROWS*DIM];
__device__ float    g_h     [ROWS*DIM];
__device__ float    g_ln    [ROWS*DIM];
__device__ float    g_qkv   [ROWS*3*DIM];
__device__ float    g_attno [ROWS*DIM];
__device__ float    g_cls   [BATCH*DIM];
__device__ unsigned gAh[384*MPAD],  gAl[384*MPAD];    // split activations (K<=768)
__device__ unsigned gMh[1536*MPAD], gMl[1536*MPAD];   // split MLP mid (K=3072)
__device__ unsigned gWh[1179648],   gWl[1179648];     // split weights (max 384*3072)

// ---------------- helpers ----------------
__device__ __forceinline__ float gelu_exact(float x) {
    return 0.5f * x * (1.0f + erff(x * 0.70710678118654752f));
}
// pack two floats as f16x2: first arg -> low 16 bits (even k)
__device__ __forceinline__ unsigned pack2h(float lo, float hi) {
    unsigned r;
    asm("cvt.rn.f16x2.f32 %0, %1, %2;" : "=r"(r) : "f"(hi), "f"(lo));
    return r;
}
__device__ __forceinline__ float f16hi_of(float x) {
    __half h = __float2half_rn(x);
    return __half2float(h);
}

// block reduce over 256 threads. do_max=true -> max else sum.
__device__ __forceinline__ float blk_reduce256(float v, bool do_max, float* red) {
    #pragma unroll
    for (int off = 16; off; off >>= 1) {
        float o = __shfl_xor_sync(0xffffffffu, v, off);
        v = do_max ? fmaxf(v, o) : (v + o);
    }
    int w = threadIdx.x >> 5;
    if ((threadIdx.x & 31) == 0) red[w] = v;
    __syncthreads();
    if (threadIdx.x < 32) {
        v = red[threadIdx.x & 7];
        #pragma unroll
        for (int off = 4; off; off >>= 1) {
            float o = __shfl_xor_sync(0xffffffffu, v, off);
            v = do_max ? fmaxf(v, o) : (v + o);
        }
        if (threadIdx.x == 0) red[0] = v;
    }
    __syncthreads();
    float r = red[0];
    __syncthreads();
    return r;
}

// ---------------- patch gather ----------------
__global__ void gather_patches_kernel(const float* __restrict__ x, float* __restrict__ P) {
    int idx = blockIdx.x * blockDim.x + threadIdx.x;
    int total = PROWS * DIM;
    if (idx >= total) return;
    int m = idx / DIM, k = idx - m * DIM;
    int b = m / NPATCH, t = m - b * NPATCH;
    int ph = t / 14, pw = t - ph * 14;
    int c = k >> 8, r = k & 255;
    int py = r >> 4, px = r & 15;
    int h = ph * 16 + py, w = pw * 16 + px;
    P[idx] = x[(((long)b * 3 + c) * 224 + h) * 224 + w];
}

// ---------------- assemble h = [cls ; tok] + pos ----------------
__global__ void embed_kernel(const float* __restrict__ tok, const float* __restrict__ cls,
                             const float* __restrict__ pos, float* __restrict__ h) {
    int idx = blockIdx.x * blockDim.x + threadIdx.x;
    int total = ROWS * DIM;
    if (idx >= total) return;
    int rd = idx % (NTOK * DIM);
    int b  = idx / (NTOK * DIM);
    int n  = rd / DIM, d = rd - n * DIM;
    float base = (n == 0) ? cls[d] : tok[((long)b * NPATCH + (n - 1)) * DIM + d];
    h[idx] = base + pos[n * DIM + d];
}

// ---------------- layernorm (fp32 out) ----------------
__global__ void ln_kernel(const float* __restrict__ x, long row_stride,
                          const float* __restrict__ w, const float* __restrict__ b,
                          float* __restrict__ y) {
    __shared__ float red[8];
    long row = blockIdx.x;
    const float* xr = x + row * row_stride;
    int tid = threadIdx.x;
    float v[3], s = 0.f, ss = 0.f;
    #pragma unroll
    for (int i = 0; i < 3; i++) {
        float t = xr[tid + i * 256];
        v[i] = t; s += t; ss += t * t;
    }
    s  = blk_reduce256(s,  false, red);
    ss = blk_reduce256(ss, false, red);
    float mu  = s * (1.0f / 768.0f);
    float var = ss * (1.0f / 768.0f) - mu * mu;
    float inv = rsqrtf(var + 1e-5f);
    #pragma unroll
    for (int i = 0; i < 3; i++) {
        int d = tid + i * 256;
        y[row * DIM + d] = (v[i] - mu) * inv * w[d] + b[d];
    }
}

// ---------------- split+transpose: src[M][K] fp32 -> hiT/loT [K/2][outpitch] f16x2 ----------------
__global__ __launch_bounds__(256) void split_transpose_kernel(
        const float* __restrict__ src, unsigned* __restrict__ hiT, unsigned* __restrict__ loT,
        int Mrows, int K, int outpitch) {
    __shared__ unsigned th[32][33], tl[32][33];
    int k20 = blockIdx.x * 32, m0 = blockIdx.y * 32;
    int tx = threadIdx.x & 31, ty = threadIdx.x >> 5;   // ty 0..7
    #pragma unroll
    for (int i = 0; i < 4; i++) {
        int ml = ty + i * 8;
        int m = m0 + ml, k2 = k20 + tx;
        float v0 = 0.f, v1 = 0.f;
        if (m < Mrows) {
            const float* s = src + (long)m * K + 2 * k2;
            v0 = s[0]; v1 = s[1];
        }
        float h0 = f16hi_of(v0), h1 = f16hi_of(v1);
        th[tx][ml] = pack2h(h0, h1);
        tl[tx][ml] = pack2h(v0 - h0, v1 - h1);
    }
    __syncthreads();
    #pragma unroll
    for (int i = 0; i < 4; i++) {
        int k2l = ty + i * 8;
        long o = (long)(k20 + k2l) * outpitch + m0 + tx;
        hiT[o] = th[k2l][tx];
        loT[o] = tl[k2l][tx];
    }
}

// ---------------- 3-term FP16-split tensor-core GEMM (pre-split operands) ----------------
// C[M,N] = A[M,K] @ W[N,K]^T; A = aH+aL exact, W = wH+wL (wL subnormal-limited).
// product = aL*wH + aH*wL + aH*wH. block 128x128x16, 8 warps, warp 64x32 m16n8k16.
#define BM 128
#define BN 128
#define SPITCH 136   // uint pitch; conflict-free fragment loads

__global__ __launch_bounds__(256) void gemm_tc_kernel(
        const unsigned* __restrict__ Ah, const unsigned* __restrict__ Al, int pitchA,
        const unsigned* __restrict__ Wh, const unsigned* __restrict__ Wl, int pitchW,
        const float* __restrict__ bias, const float* __restrict__ resid,
        float* __restrict__ C,
        unsigned* __restrict__ ChiT, unsigned* __restrict__ CloT, int pitchC,
        int M, int N, int K, int act, int splitout) {
    __shared__ unsigned AsH[8][SPITCH];
    __shared__ unsigned AsL[8][SPITCH];
    __shared__ unsigned WsH[8][SPITCH];
    __shared__ unsigned WsL[8][SPITCH];

    int bm = blockIdx.y * BM;
    int bn = blockIdx.x * BN;
    int tid  = threadIdx.x;
    int warp = tid >> 5;
    int lane = tid & 31;
    int g    = lane >> 2;    // 0..7
    int t4   = lane & 3;     // 0..3
    int wm = (warp & 1) * 64;
    int wn = (warp >> 1) * 32;

    // load coords: thread covers one uint4 (16B) per array per k16 tile
    int k2row = tid >> 5;            // 0..7
    int mcol  = (lane) << 2;         // 0..124
    const unsigned* pAh = Ah + (long)k2row * pitchA + bm + mcol;
    const unsigned* pAl = Al + (long)k2row * pitchA + bm + mcol;
    const unsigned* pWh = Wh + (long)k2row * pitchW + bn + mcol;
    const unsigned* pWl = Wl + (long)k2row * pitchW + bn + mcol;

    float acc[4][4][4];
    #pragma unroll
    for (int i = 0; i < 4; i++)
        #pragma unroll
        for (int j = 0; j < 4; j++)
            #pragma unroll
            for (int c = 0; c < 4; c++) acc[i][j][c] = 0.f;

    int T = K >> 4;
    // prefetch tile 0
    uint4 rAh = *(const uint4*)pAh;
    uint4 rAl = *(const uint4*)pAl;
    uint4 rWh = *(const uint4*)pWh;
    uint4 rWl = *(const uint4*)pWl;

    for (int t = 0; t < T; t++) {
        *(uint4*)&AsH[k2row][mcol] = rAh;
        *(uint4*)&AsL[k2row][mcol] = rAl;
        *(uint4*)&WsH[k2row][mcol] = rWh;
        *(uint4*)&WsL[k2row][mcol] = rWl;
        __syncthreads();

        if (t + 1 < T) {
            long o = (long)(t + 1) * 8;
            rAh = *(const uint4*)(pAh + o * pitchA);
            rAl = *(const uint4*)(pAl + o * pitchA);
            rWh = *(const uint4*)(pWh + o * pitchW);
            rWl = *(const uint4*)(pWl + o * pitchW);
        }

        unsigned afH[4][4], afL[4][4];
        unsigned bfH[4][2], bfL[4][2];
        #pragma unroll
        for (int mt = 0; mt < 4; mt++) {
            int m0 = wm + mt * 16;
            afH[mt][0] = AsH[t4    ][m0 + g    ];
            afH[mt][1] = AsH[t4    ][m0 + g + 8];
            afH[mt][2] = AsH[t4 + 4][m0 + g    ];
            afH[mt][3] = AsH[t4 + 4][m0 + g + 8];
            afL[mt][0] = AsL[t4    ][m0 + g    ];
            afL[mt][1] = AsL[t4    ][m0 + g + 8];
            afL[mt][2] = AsL[t4 + 4][m0 + g    ];
            afL[mt][3] = AsL[t4 + 4][m0 + g + 8];
        }
        #pragma unroll
        for (int nt = 0; nt < 4; nt++) {
            int n0 = wn + nt * 8;
            bfH[nt][0] = WsH[t4    ][n0 + g];
            bfH[nt][1] = WsH[t4 + 4][n0 + g];
            bfL[nt][0] = WsL[t4    ][n0 + g];
            bfL[nt][1] = WsL[t4 + 4][n0 + g];
        }
        #pragma unroll
        for (int mt = 0; mt < 4; mt++)
            #pragma unroll
            for (int nt = 0; nt < 4; nt++) {
                asm volatile(
                    "mma.sync.aligned.m16n8k16.row.col.f32.f16.f16.f32 "
                    "{%0,%1,%2,%3}, {%4,%5,%6,%7}, {%8,%9}, {%0,%1,%2,%3};"
                    : "+f"(acc[mt][nt][0]), "+f"(acc[mt][nt][1]),
                      "+f"(acc[mt][nt][2]), "+f"(acc[mt][nt][3])
                    : "r"(afL[mt][0]), "r"(afL[mt][1]), "r"(afL[mt][2]), "r"(afL[mt][3]),
                      "r"(bfH[nt][0]), "r"(bfH[nt][1]));
                asm volatile(
                    "mma.sync.aligned.m16n8k16.row.col.f32.f16.f16.f32 "
                    "{%0,%1,%2,%3}, {%4,%5,%6,%7}, {%8,%9}, {%0,%1,%2,%3};"
                    : "+f"(acc[mt][nt][0]), "+f"(acc[mt][nt][1]),
                      "+f"(acc[mt][nt][2]), "+f"(acc[mt][nt][3])
                    : "r"(afH[mt][0]), "r"(afH[mt][1]), "r"(afH[mt][2]), "r"(afH[mt][3]),
                      "r"(bfL[nt][0]), "r"(bfL[nt][1]));
                asm volatile(
                    "mma.sync.aligned.m16n8k16.row.col.f32.f16.f16.f32 "
                    "{%0,%1,%2,%3}, {%4,%5,%6,%7}, {%8,%9}, {%0,%1,%2,%3};"
                    : "+f"(acc[mt][nt][0]), "+f"(acc[mt][nt][1]),
                      "+f"(acc[mt][nt][2]), "+f"(acc[mt][nt][3])
                    : "r"(afH[mt][0]), "r"(afH[mt][1]), "r"(afH[mt][2]), "r"(afH[mt][3]),
                      "r"(bfH[nt][0]), "r"(bfH[nt][1]));
            }
        __syncthreads();
    }

    // epilogue
    #pragma unroll
    for (int mt = 0; mt < 4; mt++) {
        int row0 = bm + wm + mt * 16 + g;
        int row1 = row0 + 8;
        #pragma unroll
        for (int nt = 0; nt < 4; nt++) {
            int col = bn + wn + nt * 8 + t4 * 2;
            float bs0 = 0.f, bs1 = 0.f;
            if (bias && col < N)     bs0 = bias[col];
            if (bias && col + 1 < N) bs1 = bias[col + 1];
            #pragma unroll
            for (int half = 0; half < 2; half++) {
                int row = half ? row1 : row0;
                if (row >= M) continue;
                float v0 = acc[mt][nt][half * 2 + 0] + bs0;
                float v1 = acc[mt][nt][half * 2 + 1] + bs1;
                if (resid) {
                    if (col < N)     v0 += resid[(long)row * N + col];
                    if (col + 1 < N) v1 += resid[(long)row * N + col + 1];
                }
                if (act == 1) { v0 = gelu_exact(v0); v1 = gelu_exact(v1); }
                if (splitout) {
                    float h0 = f16hi_of(v0), h1 = f16hi_of(v1);
                    long o = (long)(col >> 1) * pitchC + row;
                    ChiT[o] = pack2h(h0, h1);
                    CloT[o] = pack2h(v0 - h0, v1 - h1);
                } else {
                    if (col < N)     C[(long)row * N + col]     = v0;
                    if (col + 1 < N) C[(long)row * N + col + 1] = v1;
                }
            }
        }
    }
}

// ---------------- attention: one block per (b,h) ----------------
// K stored TRANSPOSED in smem (KsT[d][n], pitch KP=200) so the QK inner loop
// reads KsT[d*KP + tid] -> consecutive lanes hit consecutive banks (was a
// 32-way conflict with row-major Ks).
#define ATTN_SMEM_FLOATS (HD*KP + NTOK*HD + 64 + 208 + 256 + 8)
__global__ __launch_bounds__(256) void attn_kernel(
        const float* __restrict__ qkv, float* __restrict__ o,
        const float* __restrict__ alpha, const float* __restrict__ beta,
        const float* __restrict__ gamma, int poly) {
    extern __shared__ float sh[];
    float* KsT    = sh;                 // [HD][KP]
    float* Vs     = KsT + HD * KP;      // [NTOK][HD]
    float* qs     = Vs + NTOK * HD;
    float* scores = qs + 64;
    float* part   = scores + 208;
    float* red    = part + 256;

    int b = blockIdx.x / HEADS;
    int hh = blockIdx.x - b * HEADS;
    int tid = threadIdx.x;

    const float* kbase = qkv + (long)(b * NTOK) * (3 * DIM) + DIM + hh * HD;
    const float* vbase = kbase + DIM;
    // stage K (transposed) and V
    for (int i = tid; i < NTOK * (HD / 4); i += 256) {
        int n = i >> 4, d4 = (i & 15) << 2;
        float4 kv = *(const float4*)(kbase + (long)n * (3 * DIM) + d4);
        KsT[(d4 + 0) * KP + n] = kv.x;
        KsT[(d4 + 1) * KP + n] = kv.y;
        KsT[(d4 + 2) * KP + n] = kv.z;
        KsT[(d4 + 3) * KP + n] = kv.w;
        ((float4*)Vs)[i] = *(const float4*)(vbase + (long)n * (3 * DIM) + d4);
    }
    float ah = alpha[hh], bh = beta[hh], gh = gamma[hh];
    __syncthreads();

    for (int n = 0; n < NTOK; n++) {
        const float* qrow = qkv + (long)(b * NTOK + n) * (3 * DIM) + hh * HD;
        if (tid < HD) qs[tid] = qrow[tid];
        __syncthreads();

        float sraw = 0.f;
        if (tid < NTOK) {
            const float* kc = KsT + tid;
            float d0 = 0.f;
            #pragma unroll 16
            for (int d = 0; d < HD; d++) d0 = fmaf(qs[d], kc[d * KP], d0);
            sraw = d0 * ATTN_SCALE;
        }

        float denom;
        if (poly) {
            float val = 0.f;
            if (tid < NTOK) {
                val = fmaxf(fmaf(ah * sraw, sraw, fmaf(bh, sraw, gh)), 0.f);
                scores[tid] = val;
            }
            denom = blk_reduce256(tid < NTOK ? val : 0.f, false, red) + 1e-6f;
        } else {
            float mx = blk_reduce256(tid < NTOK ? sraw : -1e30f, true, red);
            float p = 0.f;
            if (tid < NTOK) { p = __expf(sraw - mx); scores[tid] = p; }
            denom = blk_reduce256(p, false, red);
        }
        float inv = 1.0f / denom;

        int ch = tid >> 6, d = tid & 63;
        float a0 = 0.f;
        int m0 = ch * 50, m1 = m0 + 50; if (m1 > NTOK) m1 = NTOK;
        #pragma unroll 4
        for (int m = m0; m < m1; m++) a0 = fmaf(scores[m], Vs[m * HD + d], a0);
        part[ch * 64 + d] = a0;
        __syncthreads();
        if (tid < 64) {
            float t = part[tid] + part[64 + tid] + part[128 + tid] + part[192 + tid];
            o[(long)(b * NTOK + n) * DIM + hh * HD + tid] = t * inv;
        }
        __syncthreads();
    }
}

// ---------------- host ----------------
static inline dim3 gemm_grid(int M, int NPADv) {
    return dim3(NPADv / BN, (M + BM - 1) / BM);
}
static inline dim3 split_grid(int M, int K) {
    return dim3(K / 64, (M + 31) / 32);
}

extern "C" void kernel_launch(void* const* d_in, const int* in_sizes, int n_in,
                              void* d_out, int out_size) {
    const float* x        = (const float*)d_in[0];
    const float* patch_w  = (const float*)d_in[1];
    const float* patch_b  = (const float*)d_in[2];
    const float* cls_tok  = (const float*)d_in[3];
    const float* pos_emb  = (const float*)d_in[4];
    const float* ln1_w    = (const float*)d_in[5];
    const float* ln1_b    = (const float*)d_in[6];
    const float* qkv_w    = (const float*)d_in[7];
    const float* proj_w   = (const float*)d_in[8];
    const float* proj_b   = (const float*)d_in[9];
    const float* ln2_w    = (const float*)d_in[10];
    const float* ln2_b    = (const float*)d_in[11];
    const float* mlp_w1   = (const float*)d_in[12];
    const float* mlp_b1   = (const float*)d_in[13];
    const float* mlp_w2   = (const float*)d_in[14];
    const float* mlp_b2   = (const float*)d_in[15];
    const float* alpha    = (const float*)d_in[16];
    const float* beta     = (const float*)d_in[17];
    const float* gamma    = (const float*)d_in[18];
    const float* norm_w   = (const float*)d_in[19];
    const float* norm_b   = (const float*)d_in[20];
    const float* head_w   = (const float*)d_in[21];
    const float* head_b   = (const float*)d_in[22];
    float* out = (float*)d_out;

    float *ph, *hh, *lnb, *qkvb, *ob, *clsb;
    unsigned *ah, *al, *mh, *ml, *wh, *wl;
    cudaGetSymbolAddress((void**)&ph,   g_patches);
    cudaGetSymbolAddress((void**)&hh,   g_h);
    cudaGetSymbolAddress((void**)&lnb,  g_ln);
    cudaGetSymbolAddress((void**)&qkvb, g_qkv);
    cudaGetSymbolAddress((void**)&ob,   g_attno);
    cudaGetSymbolAddress((void**)&clsb, g_cls);
    cudaGetSymbolAddress((void**)&ah,   gAh);
    cudaGetSymbolAddress((void**)&al,   gAl);
    cudaGetSymbolAddress((void**)&mh,   gMh);
    cudaGetSymbolAddress((void**)&ml,   gMl);
    cudaGetSymbolAddress((void**)&wh,   gWh);
    cudaGetSymbolAddress((void**)&wl,   gWl);

    const int attn_smem = ATTN_SMEM_FLOATS * sizeof(float);
    cudaFuncSetAttribute(attn_kernel, cudaFuncAttributeMaxDynamicSharedMemorySize, attn_smem);

    // 1) patchify -> split -> patch GEMM -> embed
    {
        int total = PROWS * DIM;
        gather_patches_kernel<<<(total + 255) / 256, 256>>>(x, ph);
        split_transpose_kernel<<<split_grid(PROWS, 768), 256>>>(ph, ah, al, PROWS, 768, MPAD);
        split_transpose_kernel<<<split_grid(768, 768), 256>>>(patch_w, wh, wl, 768, 768, 768);
        gemm_tc_kernel<<<gemm_grid(PROWS, 768), 256>>>(ah, al, MPAD, wh, wl, 768,
                                                       patch_b, nullptr, qkvb,
                                                       nullptr, nullptr, 0,
                                                       PROWS, 768, 768, 0, 0);
        int tot2 = ROWS * DIM;
        embed_kernel<<<(tot2 + 255) / 256, 256>>>(qkvb, cls_tok, pos_emb, hh);
    }

    // 2) transformer layers
    for (int i = 0; i < DEPTH; i++) {
        int poly = (i % 2 == 0) ? 1 : 0;   // MASK = (T,F,T,F,...)
        // --- attention block ---
        ln_kernel<<<ROWS, 256>>>(hh, DIM, ln1_w + (long)i * DIM, ln1_b + (long)i * DIM, lnb);
        split_transpose_kernel<<<split_grid(ROWS, 768), 256>>>(lnb, ah, al, ROWS, 768, MPAD);
        split_transpose_kernel<<<split_grid(2304, 768), 256>>>(qkv_w + (long)i * 3 * DIM * DIM,
                                                               wh, wl, 2304, 768, 2304);
        gemm_tc_kernel<<<gemm_grid(ROWS, 2304), 256>>>(ah, al, MPAD, wh, wl, 2304,
                                                       nullptr, nullptr, qkvb,
                                                       nullptr, nullptr, 0,
                                                       ROWS, 2304, 768, 0, 0);
        attn_kernel<<<BATCH * HEADS, 256, attn_smem>>>(qkvb, ob,
                                                       alpha + (long)i * HEADS,
                                                       beta  + (long)i * HEADS,
                                                       gamma + (long)i * HEADS, poly);
        split_transpose_kernel<<<split_grid(ROWS, 768), 256>>>(ob, ah, al, ROWS, 768, MPAD);
        split_transpose_kernel<<<split_grid(768, 768), 256>>>(proj_w + (long)i * DIM * DIM,
                                                              wh, wl, 768, 768, 768);
        gemm_tc_kernel<<<gemm_grid(ROWS, 768), 256>>>(ah, al, MPAD, wh, wl, 768,
                                                      proj_b + (long)i * DIM, hh, hh,
                                                      nullptr, nullptr, 0,
                                                      ROWS, 768, 768, 0, 0);
        // --- MLP block ---
        ln_kernel<<<ROWS, 256>>>(hh, DIM, ln2_w + (long)i * DIM, ln2_b + (long)i * DIM, lnb);
        split_transpose_kernel<<<split_grid(ROWS, 768), 256>>>(lnb, ah, al, ROWS, 768, MPAD);
        split_transpose_kernel<<<split_grid(3072, 768), 256>>>(mlp_w1 + (long)i * MLPD * DIM,
                                                               wh, wl, 3072, 768, 3072);
        gemm_tc_kernel<<<gemm_grid(ROWS, 3072), 256>>>(ah, al, MPAD, wh, wl, 3072,
                                                       mlp_b1 + (long)i * MLPD, nullptr, nullptr,
                                                       mh, ml, MPAD,
                                                       ROWS, 3072, 768, 1 /*gelu*/, 1 /*splitout*/);
        split_transpose_kernel<<<split_grid(768, 3072), 256>>>(mlp_w2 + (long)i * DIM * MLPD,
                                                               wh, wl, 768, 3072, 768);
        gemm_tc_kernel<<<gemm_grid(ROWS, 768), 256>>>(mh, ml, MPAD, wh, wl, 768,
                                                      mlp_b2 + (long)i * DIM, hh, hh,
                                                      nullptr, nullptr, 0,
                                                      ROWS, 768, 3072, 0, 0);
    }

    // 3) final LN on cls rows + head
    ln_kernel<<<BATCH, 256>>>(hh, (long)NTOK * DIM, norm_w, norm_b, clsb);
    split_transpose_kernel<<<split_grid(BATCH, 768), 256>>>(clsb, ah, al, BATCH, 768, MPAD);
    split_transpose_kernel<<<split_grid(1000, 768), 256>>>(head_w, wh, wl, 1000, 768, 1024);
    gemm_tc_kernel<<<gemm_grid(BATCH, 1024), 256>>>(ah, al, MPAD, wh, wl, 1024,
                                                    head_b, nullptr, out,
                                                    nullptr, nullptr, 0,
                                                    BATCH, 1000, 768, 0, 0);
}

// round 17
// speedup vs baseline: 1.6423x; 1.0382x over previous
#include <cuda_runtime.h>
#include <cuda_fp16.h>
#include <math.h>

#define BATCH   32
#define NTOK    197
#define DIM     768
#define HEADS   12
#define HD      64
#define MLPD    3072
#define DEPTH   12
#define ROWS    (BATCH*NTOK)     // 6304
#define NPATCH  196
#define PROWS   (BATCH*NPATCH)   // 6272
#define ATTN_SCALE 0.125f
#define MPAD    6400             // padded M for split activation buffers
#define KP      200              // KsT pitch (floats)

// ---------------- scratch (no cudaMalloc allowed) ----------------
__device__ float    g_patches[PROWS*DIM];
__device__ float    g_h     [ROWS*DIM];
__device__ float    g_ln    [ROWS*DIM];
__device__ float    g_qkv   [ROWS*3*DIM];
__device__ float    g_attno [ROWS*DIM];
__device__ float    g_cls   [BATCH*DIM];
__device__ unsigned gAh[384*MPAD],  gAl[384*MPAD];    // split activations (K<=768)
__device__ unsigned gMh[1536*MPAD], gMl[1536*MPAD];   // split MLP mid (K=3072)
__device__ unsigned gWh[1179648],   gWl[1179648];     // split weights (max 384*3072)

// ---------------- helpers ----------------
__device__ __forceinline__ float gelu_exact(float x) {
    return 0.5f * x * (1.0f + erff(x * 0.70710678118654752f));
}
// pack two floats as f16x2: first arg -> low 16 bits (even k)
__device__ __forceinline__ unsigned pack2h(float lo, float hi) {
    unsigned r;
    asm("cvt.rn.f16x2.f32 %0, %1, %2;" : "=r"(r) : "f"(hi), "f"(lo));
    return r;
}
__device__ __forceinline__ float f16hi_of(float x) {
    __half h = __float2half_rn(x);
    return __half2float(h);
}

// block reduce over 256 threads. do_max=true -> max else sum.
__device__ __forceinline__ float blk_reduce256(float v, bool do_max, float* red) {
    #pragma unroll
    for (int off = 16; off; off >>= 1) {
        float o = __shfl_xor_sync(0xffffffffu, v, off);
        v = do_max ? fmaxf(v, o) : (v + o);
    }
    int w = threadIdx.x >> 5;
    if ((threadIdx.x & 31) == 0) red[w] = v;
    __syncthreads();
    if (threadIdx.x < 32) {
        v = red[threadIdx.x & 7];
        #pragma unroll
        for (int off = 4; off; off >>= 1) {
            float o = __shfl_xor_sync(0xffffffffu, v, off);
            v = do_max ? fmaxf(v, o) : (v + o);
        }
        if (threadIdx.x == 0) red[0] = v;
    }
    __syncthreads();
    float r = red[0];
    __syncthreads();
    return r;
}

// ---------------- patch gather ----------------
__global__ void gather_patches_kernel(const float* __restrict__ x, float* __restrict__ P) {
    int idx = blockIdx.x * blockDim.x + threadIdx.x;
    int total = PROWS * DIM;
    if (idx >= total) return;
    int m = idx / DIM, k = idx - m * DIM;
    int b = m / NPATCH, t = m - b * NPATCH;
    int ph = t / 14, pw = t - ph * 14;
    int c = k >> 8, r = k & 255;
    int py = r >> 4, px = r & 15;
    int h = ph * 16 + py, w = pw * 16 + px;
    P[idx] = x[(((long)b * 3 + c) * 224 + h) * 224 + w];
}

// ---------------- assemble h = [cls ; tok] + pos ----------------
__global__ void embed_kernel(const float* __restrict__ tok, const float* __restrict__ cls,
                             const float* __restrict__ pos, float* __restrict__ h) {
    int idx = blockIdx.x * blockDim.x + threadIdx.x;
    int total = ROWS * DIM;
    if (idx >= total) return;
    int rd = idx % (NTOK * DIM);
    int b  = idx / (NTOK * DIM);
    int n  = rd / DIM, d = rd - n * DIM;
    float base = (n == 0) ? cls[d] : tok[((long)b * NPATCH + (n - 1)) * DIM + d];
    h[idx] = base + pos[n * DIM + d];
}

// ---------------- layernorm (fp32 out) ----------------
__global__ void ln_kernel(const float* __restrict__ x, long row_stride,
                          const float* __restrict__ w, const float* __restrict__ b,
                          float* __restrict__ y) {
    __shared__ float red[8];
    long row = blockIdx.x;
    const float* xr = x + row * row_stride;
    int tid = threadIdx.x;
    float v[3], s = 0.f, ss = 0.f;
    #pragma unroll
    for (int i = 0; i < 3; i++) {
        float t = xr[tid + i * 256];
        v[i] = t; s += t; ss += t * t;
    }
    s  = blk_reduce256(s,  false, red);
    ss = blk_reduce256(ss, false, red);
    float mu  = s * (1.0f / 768.0f);
    float var = ss * (1.0f / 768.0f) - mu * mu;
    float inv = rsqrtf(var + 1e-5f);
    #pragma unroll
    for (int i = 0; i < 3; i++) {
        int d = tid + i * 256;
        y[row * DIM + d] = (v[i] - mu) * inv * w[d] + b[d];
    }
}

// ---------------- split+transpose: src[M][K] fp32 -> hiT/loT [K/2][outpitch] f16x2 ----------------
__global__ __launch_bounds__(256) void split_transpose_kernel(
        const float* __restrict__ src, unsigned* __restrict__ hiT, unsigned* __restrict__ loT,
        int Mrows, int K, int outpitch) {
    __shared__ unsigned th[32][33], tl[32][33];
    int k20 = blockIdx.x * 32, m0 = blockIdx.y * 32;
    int tx = threadIdx.x & 31, ty = threadIdx.x >> 5;   // ty 0..7
    #pragma unroll
    for (int i = 0; i < 4; i++) {
        int ml = ty + i * 8;
        int m = m0 + ml, k2 = k20 + tx;
        float v0 = 0.f, v1 = 0.f;
        if (m < Mrows) {
            const float* s = src + (long)m * K + 2 * k2;
            v0 = s[0]; v1 = s[1];
        }
        float h0 = f16hi_of(v0), h1 = f16hi_of(v1);
        th[tx][ml] = pack2h(h0, h1);
        tl[tx][ml] = pack2h(v0 - h0, v1 - h1);
    }
    __syncthreads();
    #pragma unroll
    for (int i = 0; i < 4; i++) {
        int k2l = ty + i * 8;
        long o = (long)(k20 + k2l) * outpitch + m0 + tx;
        hiT[o] = th[k2l][tx];
        loT[o] = tl[k2l][tx];
    }
}

// ---------------- 3-term FP16-split tensor-core GEMM (pre-split operands) ----------------
// C[M,N] = A[M,K] @ W[N,K]^T; A = aH+aL exact, W = wH+wL (wL subnormal-limited).
// product = aL*wH + aH*wL + aH*wH. block 128x128x16, 8 warps, warp 64x32 m16n8k16.
#define BM 128
#define BN 128
#define SPITCH 136   // uint pitch; conflict-free fragment loads

__global__ __launch_bounds__(256) void gemm_tc_kernel(
        const unsigned* __restrict__ Ah, const unsigned* __restrict__ Al, int pitchA,
        const unsigned* __restrict__ Wh, const unsigned* __restrict__ Wl, int pitchW,
        const float* __restrict__ bias, const float* __restrict__ resid,
        float* __restrict__ C,
        unsigned* __restrict__ ChiT, unsigned* __restrict__ CloT, int pitchC,
        int M, int N, int K, int act, int splitout) {
    __shared__ unsigned AsH[8][SPITCH];
    __shared__ unsigned AsL[8][SPITCH];
    __shared__ unsigned WsH[8][SPITCH];
    __shared__ unsigned WsL[8][SPITCH];

    int bm = blockIdx.y * BM;
    int bn = blockIdx.x * BN;
    int tid  = threadIdx.x;
    int warp = tid >> 5;
    int lane = tid & 31;
    int g    = lane >> 2;    // 0..7
    int t4   = lane & 3;     // 0..3
    int wm = (warp & 1) * 64;
    int wn = (warp >> 1) * 32;

    int k2row = tid >> 5;            // 0..7
    int mcol  = (lane) << 2;         // 0..124
    const unsigned* pAh = Ah + (long)k2row * pitchA + bm + mcol;
    const unsigned* pAl = Al + (long)k2row * pitchA + bm + mcol;
    const unsigned* pWh = Wh + (long)k2row * pitchW + bn + mcol;
    const unsigned* pWl = Wl + (long)k2row * pitchW + bn + mcol;

    float acc[4][4][4];
    #pragma unroll
    for (int i = 0; i < 4; i++)
        #pragma unroll
        for (int j = 0; j < 4; j++)
            #pragma unroll
            for (int c = 0; c < 4; c++) acc[i][j][c] = 0.f;

    int T = K >> 4;
    uint4 rAh = *(const uint4*)pAh;
    uint4 rAl = *(const uint4*)pAl;
    uint4 rWh = *(const uint4*)pWh;
    uint4 rWl = *(const uint4*)pWl;

    for (int t = 0; t < T; t++) {
        *(uint4*)&AsH[k2row][mcol] = rAh;
        *(uint4*)&AsL[k2row][mcol] = rAl;
        *(uint4*)&WsH[k2row][mcol] = rWh;
        *(uint4*)&WsL[k2row][mcol] = rWl;
        __syncthreads();

        if (t + 1 < T) {
            long o = (long)(t + 1) * 8;
            rAh = *(const uint4*)(pAh + o * pitchA);
            rAl = *(const uint4*)(pAl + o * pitchA);
            rWh = *(const uint4*)(pWh + o * pitchW);
            rWl = *(const uint4*)(pWl + o * pitchW);
        }

        unsigned afH[4][4], afL[4][4];
        unsigned bfH[4][2], bfL[4][2];
        #pragma unroll
        for (int mt = 0; mt < 4; mt++) {
            int m0 = wm + mt * 16;
            afH[mt][0] = AsH[t4    ][m0 + g    ];
            afH[mt][1] = AsH[t4    ][m0 + g + 8];
            afH[mt][2] = AsH[t4 + 4][m0 + g    ];
            afH[mt][3] = AsH[t4 + 4][m0 + g + 8];
            afL[mt][0] = AsL[t4    ][m0 + g    ];
            afL[mt][1] = AsL[t4    ][m0 + g + 8];
            afL[mt][2] = AsL[t4 + 4][m0 + g    ];
            afL[mt][3] = AsL[t4 + 4][m0 + g + 8];
        }
        #pragma unroll
        for (int nt = 0; nt < 4; nt++) {
            int n0 = wn + nt * 8;
            bfH[nt][0] = WsH[t4    ][n0 + g];
            bfH[nt][1] = WsH[t4 + 4][n0 + g];
            bfL[nt][0] = WsL[t4    ][n0 + g];
            bfL[nt][1] = WsL[t4 + 4][n0 + g];
        }
        #pragma unroll
        for (int mt = 0; mt < 4; mt++)
            #pragma unroll
            for (int nt = 0; nt < 4; nt++) {
                asm volatile(
                    "mma.sync.aligned.m16n8k16.row.col.f32.f16.f16.f32 "
                    "{%0,%1,%2,%3}, {%4,%5,%6,%7}, {%8,%9}, {%0,%1,%2,%3};"
                    : "+f"(acc[mt][nt][0]), "+f"(acc[mt][nt][1]),
                      "+f"(acc[mt][nt][2]), "+f"(acc[mt][nt][3])
                    : "r"(afL[mt][0]), "r"(afL[mt][1]), "r"(afL[mt][2]), "r"(afL[mt][3]),
                      "r"(bfH[nt][0]), "r"(bfH[nt][1]));
                asm volatile(
                    "mma.sync.aligned.m16n8k16.row.col.f32.f16.f16.f32 "
                    "{%0,%1,%2,%3}, {%4,%5,%6,%7}, {%8,%9}, {%0,%1,%2,%3};"
                    : "+f"(acc[mt][nt][0]), "+f"(acc[mt][nt][1]),
                      "+f"(acc[mt][nt][2]), "+f"(acc[mt][nt][3])
                    : "r"(afH[mt][0]), "r"(afH[mt][1]), "r"(afH[mt][2]), "r"(afH[mt][3]),
                      "r"(bfL[nt][0]), "r"(bfL[nt][1]));
                asm volatile(
                    "mma.sync.aligned.m16n8k16.row.col.f32.f16.f16.f32 "
                    "{%0,%1,%2,%3}, {%4,%5,%6,%7}, {%8,%9}, {%0,%1,%2,%3};"
                    : "+f"(acc[mt][nt][0]), "+f"(acc[mt][nt][1]),
                      "+f"(acc[mt][nt][2]), "+f"(acc[mt][nt][3])
                    : "r"(afH[mt][0]), "r"(afH[mt][1]), "r"(afH[mt][2]), "r"(afH[mt][3]),
                      "r"(bfH[nt][0]), "r"(bfH[nt][1]));
            }
        __syncthreads();
    }

    // epilogue
    #pragma unroll
    for (int mt = 0; mt < 4; mt++) {
        int row0 = bm + wm + mt * 16 + g;
        int row1 = row0 + 8;
        #pragma unroll
        for (int nt = 0; nt < 4; nt++) {
            int col = bn + wn + nt * 8 + t4 * 2;
            float bs0 = 0.f, bs1 = 0.f;
            if (bias && col < N)     bs0 = bias[col];
            if (bias && col + 1 < N) bs1 = bias[col + 1];
            #pragma unroll
            for (int half = 0; half < 2; half++) {
                int row = half ? row1 : row0;
                if (row >= M) continue;
                float v0 = acc[mt][nt][half * 2 + 0] + bs0;
                float v1 = acc[mt][nt][half * 2 + 1] + bs1;
                if (resid) {
                    if (col < N)     v0 += resid[(long)row * N + col];
                    if (col + 1 < N) v1 += resid[(long)row * N + col + 1];
                }
                if (act == 1) { v0 = gelu_exact(v0); v1 = gelu_exact(v1); }
                if (splitout) {
                    float h0 = f16hi_of(v0), h1 = f16hi_of(v1);
                    long o = (long)(col >> 1) * pitchC + row;
                    ChiT[o] = pack2h(h0, h1);
                    CloT[o] = pack2h(v0 - h0, v1 - h1);
                } else {
                    if (col < N)     C[(long)row * N + col]     = v0;
                    if (col + 1 < N) C[(long)row * N + col + 1] = v1;
                }
            }
        }
    }
}

// ---------------- attention: warp-per-query, no block barriers in main loop ----------------
// KsT[d][n] pitch KP (conflict-free token-indexed reads); Vs[n][d] row-major
// (conflict-free d-indexed reads). Each of 8 warps owns queries n = warp+8j.
// q held in registers; score reductions via shfl only.
#define ATTN_SMEM_FLOATS (HD*KP + NTOK*HD)
__global__ __launch_bounds__(256) void attn_kernel(
        const float* __restrict__ qkv, float* __restrict__ o,
        const float* __restrict__ alpha, const float* __restrict__ beta,
        const float* __restrict__ gamma, int poly) {
    extern __shared__ float sh[];
    float* KsT = sh;                 // [HD][KP]
    float* Vs  = KsT + HD * KP;      // [NTOK][HD]

    int b = blockIdx.x / HEADS;
    int hh = blockIdx.x - b * HEADS;
    int tid = threadIdx.x;
    int warp = tid >> 5;
    int lane = tid & 31;

    const float* kbase = qkv + (long)(b * NTOK) * (3 * DIM) + DIM + hh * HD;
    const float* vbase = kbase + DIM;
    // stage K (transposed) and V
    for (int i = tid; i < NTOK * (HD / 4); i += 256) {
        int n = i >> 4, d4 = (i & 15) << 2;
        float4 kv = *(const float4*)(kbase + (long)n * (3 * DIM) + d4);
        KsT[(d4 + 0) * KP + n] = kv.x;
        KsT[(d4 + 1) * KP + n] = kv.y;
        KsT[(d4 + 2) * KP + n] = kv.z;
        KsT[(d4 + 3) * KP + n] = kv.w;
        ((float4*)Vs)[i] = *(const float4*)(vbase + (long)n * (3 * DIM) + d4);
    }
    float ah = alpha[hh], bh = beta[hh], gh = gamma[hh];
    __syncthreads();

    for (int n = warp; n < NTOK; n += 8) {
        // q into registers (broadcast global loads, L1-resident)
        const float* qrow = qkv + (long)(b * NTOK + n) * (3 * DIM) + hh * HD;
        float qreg[HD];
        #pragma unroll
        for (int d = 0; d < HD; d += 4) {
            float4 qv = *(const float4*)(qrow + d);
            qreg[d] = qv.x; qreg[d+1] = qv.y; qreg[d+2] = qv.z; qreg[d+3] = qv.w;
        }

        // scores: lane handles tokens t = lane + 32*j (j=0..6)
        float sc[7];
        #pragma unroll
        for (int j = 0; j < 7; j++) {
            int t = lane + 32 * j;
            float s = 0.f;
            if (t < NTOK) {
                const float* kc = KsT + t;
                #pragma unroll
                for (int d = 0; d < HD; d++) s = fmaf(qreg[d], kc[d * KP], s);
            }
            sc[j] = s * ATTN_SCALE;
        }

        float denom;
        if (poly) {
            float psum = 0.f;
            #pragma unroll
            for (int j = 0; j < 7; j++) {
                int t = lane + 32 * j;
                float val = 0.f;
                if (t < NTOK)
                    val = fmaxf(fmaf(ah * sc[j], sc[j], fmaf(bh, sc[j], gh)), 0.f);
                sc[j] = val;
                psum += val;
            }
            #pragma unroll
            for (int off = 16; off; off >>= 1)
                psum += __shfl_xor_sync(0xffffffffu, psum, off);
            denom = psum + 1e-6f;
        } else {
            float mx = -1e30f;
            #pragma unroll
            for (int j = 0; j < 7; j++) {
                int t = lane + 32 * j;
                if (t < NTOK) mx = fmaxf(mx, sc[j]);
            }
            #pragma unroll
            for (int off = 16; off; off >>= 1)
                mx = fmaxf(mx, __shfl_xor_sync(0xffffffffu, mx, off));
            float psum = 0.f;
            #pragma unroll
            for (int j = 0; j < 7; j++) {
                int t = lane + 32 * j;
                float p = (t < NTOK) ? __expf(sc[j] - mx) : 0.f;
                sc[j] = p;
                psum += p;
            }
            #pragma unroll
            for (int off = 16; off; off >>= 1)
                psum += __shfl_xor_sync(0xffffffffu, psum, off);
            denom = psum;
        }
        float inv = 1.0f / denom;

        // AV: lane accumulates output dims lane and lane+32
        float o0 = 0.f, o1 = 0.f;
        #pragma unroll 4
        for (int t = 0; t < NTOK; t++) {
            float s = __shfl_sync(0xffffffffu, sc[t >> 5], t & 31);
            const float* vr = Vs + t * HD;
            o0 = fmaf(s, vr[lane],      o0);
            o1 = fmaf(s, vr[lane + 32], o1);
        }
        float* orow = o + (long)(b * NTOK + n) * DIM + hh * HD;
        orow[lane]      = o0 * inv;
        orow[lane + 32] = o1 * inv;
    }
}

// ---------------- host ----------------
static inline dim3 gemm_grid(int M, int NPADv) {
    return dim3(NPADv / BN, (M + BM - 1) / BM);
}
static inline dim3 split_grid(int M, int K) {
    return dim3(K / 64, (M + 31) / 32);
}

extern "C" void kernel_launch(void* const* d_in, const int* in_sizes, int n_in,
                              void* d_out, int out_size) {
    const float* x        = (const float*)d_in[0];
    const float* patch_w  = (const float*)d_in[1];
    const float* patch_b  = (const float*)d_in[2];
    const float* cls_tok  = (const float*)d_in[3];
    const float* pos_emb  = (const float*)d_in[4];
    const float* ln1_w    = (const float*)d_in[5];
    const float* ln1_b    = (const float*)d_in[6];
    const float* qkv_w    = (const float*)d_in[7];
    const float* proj_w   = (const float*)d_in[8];
    const float* proj_b   = (const float*)d_in[9];
    const float* ln2_w    = (const float*)d_in[10];
    const float* ln2_b    = (const float*)d_in[11];
    const float* mlp_w1   = (const float*)d_in[12];
    const float* mlp_b1   = (const float*)d_in[13];
    const float* mlp_w2   = (const float*)d_in[14];
    const float* mlp_b2   = (const float*)d_in[15];
    const float* alpha    = (const float*)d_in[16];
    const float* beta     = (const float*)d_in[17];
    const float* gamma    = (const float*)d_in[18];
    const float* norm_w   = (const float*)d_in[19];
    const float* norm_b   = (const float*)d_in[20];
    const float* head_w   = (const float*)d_in[21];
    const float* head_b   = (const float*)d_in[22];
    float* out = (float*)d_out;

    float *ph, *hh, *lnb, *qkvb, *ob, *clsb;
    unsigned *ah, *al, *mh, *ml, *wh, *wl;
    cudaGetSymbolAddress((void**)&ph,   g_patches);
    cudaGetSymbolAddress((void**)&hh,   g_h);
    cudaGetSymbolAddress((void**)&lnb,  g_ln);
    cudaGetSymbolAddress((void**)&qkvb, g_qkv);
    cudaGetSymbolAddress((void**)&ob,   g_attno);
    cudaGetSymbolAddress((void**)&clsb, g_cls);
    cudaGetSymbolAddress((void**)&ah,   gAh);
    cudaGetSymbolAddress((void**)&al,   gAl);
    cudaGetSymbolAddress((void**)&mh,   gMh);
    cudaGetSymbolAddress((void**)&ml,   gMl);
    cudaGetSymbolAddress((void**)&wh,   gWh);
    cudaGetSymbolAddress((void**)&wl,   gWl);

    const int attn_smem = ATTN_SMEM_FLOATS * sizeof(float);
    cudaFuncSetAttribute(attn_kernel, cudaFuncAttributeMaxDynamicSharedMemorySize, attn_smem);

    // 1) patchify -> split -> patch GEMM -> embed
    {
        int total = PROWS * DIM;
        gather_patches_kernel<<<(total + 255) / 256, 256>>>(x, ph);
        split_transpose_kernel<<<split_grid(PROWS, 768), 256>>>(ph, ah, al, PROWS, 768, MPAD);
        split_transpose_kernel<<<split_grid(768, 768), 256>>>(patch_w, wh, wl, 768, 768, 768);
        gemm_tc_kernel<<<gemm_grid(PROWS, 768), 256>>>(ah, al, MPAD, wh, wl, 768,
                                                       patch_b, nullptr, qkvb,
                                                       nullptr, nullptr, 0,
                                                       PROWS, 768, 768, 0, 0);
        int tot2 = ROWS * DIM;
        embed_kernel<<<(tot2 + 255) / 256, 256>>>(qkvb, cls_tok, pos_emb, hh);
    }

    // 2) transformer layers
    for (int i = 0; i < DEPTH; i++) {
        int poly = (i % 2 == 0) ? 1 : 0;   // MASK = (T,F,T,F,...)
        // --- attention block ---
        ln_kernel<<<ROWS, 256>>>(hh, DIM, ln1_w + (long)i * DIM, ln1_b + (long)i * DIM, lnb);
        split_transpose_kernel<<<split_grid(ROWS, 768), 256>>>(lnb, ah, al, ROWS, 768, MPAD);
        split_transpose_kernel<<<split_grid(2304, 768), 256>>>(qkv_w + (long)i * 3 * DIM * DIM,
                                                               wh, wl, 2304, 768, 2304);
        gemm_tc_kernel<<<gemm_grid(ROWS, 2304), 256>>>(ah, al, MPAD, wh, wl, 2304,
                                                       nullptr, nullptr, qkvb,
                                                       nullptr, nullptr, 0,
                                                       ROWS, 2304, 768, 0, 0);
        attn_kernel<<<BATCH * HEADS, 256, attn_smem>>>(qkvb, ob,
                                                       alpha + (long)i * HEADS,
                                                       beta  + (long)i * HEADS,
                                                       gamma + (long)i * HEADS, poly);
        split_transpose_kernel<<<split_grid(ROWS, 768), 256>>>(ob, ah, al, ROWS, 768, MPAD);
        split_transpose_kernel<<<split_grid(768, 768), 256>>>(proj_w + (long)i * DIM * DIM,
                                                              wh, wl, 768, 768, 768);
        gemm_tc_kernel<<<gemm_grid(ROWS, 768), 256>>>(ah, al, MPAD, wh, wl, 768,
                                                      proj_b + (long)i * DIM, hh, hh,
                                                      nullptr, nullptr, 0,
                                                      ROWS, 768, 768, 0, 0);
        // --- MLP block ---
        ln_kernel<<<ROWS, 256>>>(hh, DIM, ln2_w + (long)i * DIM, ln2_b + (long)i * DIM, lnb);
        split_transpose_kernel<<<split_grid(ROWS, 768), 256>>>(lnb, ah, al, ROWS, 768, MPAD);
        split_transpose_kernel<<<split_grid(3072, 768), 256>>>(mlp_w1 + (long)i * MLPD * DIM,
                                                               wh, wl, 3072, 768, 3072);
        gemm_tc_kernel<<<gemm_grid(ROWS, 3072), 256>>>(ah, al, MPAD, wh, wl, 3072,
                                                       mlp_b1 + (long)i * MLPD, nullptr, nullptr,
                                                       mh, ml, MPAD,
                                                       ROWS, 3072, 768, 1 /*gelu*/, 1 /*splitout*/);
        split_transpose_kernel<<<split_grid(768, 3072), 256>>>(mlp_w2 + (long)i * DIM * MLPD,
                                                               wh, wl, 768, 3072, 768);
        gemm_tc_kernel<<<gemm_grid(ROWS, 768), 256>>>(mh, ml, MPAD, wh, wl, 768,
                                                      mlp_b2 + (long)i * DIM, hh, hh,
                                                      nullptr, nullptr, 0,
                                                      ROWS, 768, 3072, 0, 0);
    }

    // 3) final LN on cls rows + head
    ln_kernel<<<BATCH, 256>>>(hh, (long)NTOK * DIM, norm_w, norm_b, clsb);
    split_transpose_kernel<<<split_grid(BATCH, 768), 256>>>(clsb, ah, al, BATCH, 768, MPAD);
    split_transpose_kernel<<<split_grid(1000, 768), 256>>>(head_w, wh, wl, 1000, 768, 1024);
    gemm_tc_kernel<<<gemm_grid(BATCH, 1024), 256>>>(ah, al, MPAD, wh, wl, 1024,
                                                    head_b, nullptr, out,
                                                    nullptr, nullptr, 0,
                                                    BATCH, 1000, 768, 0, 0);
}